// round 16
// baseline (speedup 1.0000x reference)
#include <cuda_runtime.h>
#include <cuda_fp16.h>
#include <math.h>

#define BT   4096
#define HID  1024
#define TSEQ 2048
#define KVW  512
#define HD   64

// fp16 scratch (device globals — no allocation allowed)
__device__ __align__(256) half g_xh[(size_t)BT * HID];
__device__ __align__(256) half g_wqh[(size_t)HID * HID];
__device__ __align__(256) half g_wkvh[(size_t)HID * KVW];
__device__ __align__(256) half g_woh[(size_t)HID * HID];
__device__ __align__(256) half g_qh[(size_t)BT * HID];
__device__ __align__(256) half g_kvh[(size_t)BT * KVW];
__device__ __align__(256) half g_atth[(size_t)BT * HID];

// ---------------------------------------------------------------------------
// helpers
// ---------------------------------------------------------------------------
__device__ __forceinline__ unsigned f2h2(float a, float b) {
    half2 h = __float22half2_rn(make_float2(a, b));
    return *(unsigned*)&h;
}
__device__ __forceinline__ void mma16(float* d, const unsigned* a, const unsigned* b) {
    asm volatile(
        "mma.sync.aligned.m16n8k16.row.col.f32.f16.f16.f32 "
        "{%0,%1,%2,%3},{%4,%5,%6,%7},{%8,%9},{%0,%1,%2,%3};\n"
        : "+f"(d[0]), "+f"(d[1]), "+f"(d[2]), "+f"(d[3])
        : "r"(a[0]), "r"(a[1]), "r"(a[2]), "r"(a[3]), "r"(b[0]), "r"(b[1]));
}
__device__ __forceinline__ void ldsm4(unsigned* r, unsigned addr) {
    asm volatile("ldmatrix.sync.aligned.m8n8.x4.shared.b16 {%0,%1,%2,%3}, [%4];"
                 : "=r"(r[0]), "=r"(r[1]), "=r"(r[2]), "=r"(r[3]) : "r"(addr));
}
__device__ __forceinline__ void ldsm4t(unsigned* r, unsigned addr) {
    asm volatile("ldmatrix.sync.aligned.m8n8.x4.trans.shared.b16 {%0,%1,%2,%3}, [%4];"
                 : "=r"(r[0]), "=r"(r[1]), "=r"(r[2]), "=r"(r[3]) : "r"(addr));
}
__device__ __forceinline__ unsigned sptr(const void* p) {
    return (unsigned)__cvta_generic_to_shared(p);
}
__device__ __forceinline__ void cpa16(unsigned dst, const void* src) {
    asm volatile("cp.async.cg.shared.global [%0], [%1], 16;" :: "r"(dst), "l"(src));
}
__device__ __forceinline__ void cp_commit() {
    asm volatile("cp.async.commit_group;");
}
template<int N> __device__ __forceinline__ void cp_wait() {
    asm volatile("cp.async.wait_group %0;" :: "n"(N));
}

// ---------------------------------------------------------------------------
// fused fp32 -> fp16 convert for all 4 tensors (one launch)
// ---------------------------------------------------------------------------
#define CN0 (BT * HID / 4)     // x
#define CN1 (HID * HID / 4)    // Wq
#define CN2 (HID * KVW / 4)    // Wkv
#define CN3 (HID * HID / 4)    // Wo
#define CNT (CN0 + CN1 + CN2 + CN3)

__global__ __launch_bounds__(256) void conv_all(
    const float4* __restrict__ x,  const float4* __restrict__ wq,
    const float4* __restrict__ wkv, const float4* __restrict__ wo,
    uint2* __restrict__ xh, uint2* __restrict__ wqh,
    uint2* __restrict__ wkvh, uint2* __restrict__ woh)
{
    int i = blockIdx.x * 256 + threadIdx.x;
    const float4* src;
    uint2* dst;
    int j;
    if (i < CN0)                  { src = x;   dst = xh;   j = i; }
    else if (i < CN0 + CN1)       { src = wq;  dst = wqh;  j = i - CN0; }
    else if (i < CN0 + CN1 + CN2) { src = wkv; dst = wkvh; j = i - CN0 - CN1; }
    else if (i < CNT)             { src = wo;  dst = woh;  j = i - CN0 - CN1 - CN2; }
    else return;
    float4 v = src[j];
    dst[j] = make_uint2(f2h2(v.x, v.y), f2h2(v.z, v.w));
}

// ---------------------------------------------------------------------------
// fp16 GEMM, cp.async 3-stage, BK=64.
// C[M,N] = A[M,K] @ B[K,N]. BM=128, BN=64, BK=64, 256 thr, 8 warps (4m x 2n).
// ---------------------------------------------------------------------------
#define GAS 72   // sA row stride (halves): 64 + 8 pad (144B rows)
#define GBS 72   // sB row stride (halves): 64 + 8 pad
#define SA_ST (128 * GAS)
#define SB_ST (64 * GBS)
#define GSMEM ((3 * (SA_ST + SB_ST)) * 2)   // bytes (3 stages)

template<bool HALF_OUT>
__device__ __forceinline__ void gemm_core(
    const half* __restrict__ A, const half* __restrict__ B,
    void* __restrict__ Cv, int m0, int n0, int N, int K,
    half* sA, half* sB)
{
    const int t = threadIdx.x, lane = t & 31, warp = t >> 5;
    const int wm = warp & 3, wn = warp >> 2;
    const int g = lane >> 2, tig = lane & 3;
    const int KT = K >> 6;

    const int ld_row = t >> 3, ld_ch = t & 7;   // 8 chunks (of 8 halves) per row

    auto issue = [&](int kt, int s) {
        int k0 = kt * 64;
        half* dA = sA + s * SA_ST;
        half* dB = sB + s * SB_ST;
        #pragma unroll
        for (int u = 0; u < 4; u++) {            // A: 128 rows x 64 halves
            int row = ld_row + u * 32;
            cpa16(sptr(&dA[row * GAS + ld_ch * 8]),
                  A + (size_t)(m0 + row) * K + k0 + ld_ch * 8);
        }
        #pragma unroll
        for (int u = 0; u < 2; u++) {            // B: 64 rows x 64 halves
            int row = ld_row + u * 32;
            cpa16(sptr(&dB[row * GBS + ld_ch * 8]),
                  B + (size_t)(k0 + row) * N + n0 + ld_ch * 8);
        }
        cp_commit();
    };

    float acc[2][4][4] = {};

    issue(0, 0);
    issue(1, 1);
    cp_wait<1>();
    __syncthreads();

    for (int kt = 0; kt < KT; kt++) {
        int cur = kt % 3;
        if (kt + 2 < KT) issue(kt + 2, (kt + 2) % 3);

        half* cA = sA + cur * SA_ST;
        half* cB = sB + cur * SB_ST;

        #pragma unroll
        for (int ks = 0; ks < 4; ks++) {
            unsigned af[2][4];
            #pragma unroll
            for (int mf = 0; mf < 2; mf++) {
                int row = wm * 32 + mf * 16 + (lane & 15);
                int col = ks * 16 + (lane >> 4) * 8;
                ldsm4(af[mf], sptr(&cA[row * GAS + col]));
            }
            #pragma unroll
            for (int nfp = 0; nfp < 2; nfp++) {
                // paired B frags (nf=2*nfp, 2*nfp+1) via one ldsm4t
                unsigned bf[4];
                int mat = lane >> 3;
                int kr = ks * 16 + (mat & 1) * 8 + (lane & 7);
                int cc = wn * 32 + nfp * 16 + (mat >> 1) * 8;
                ldsm4t(bf, sptr(&cB[kr * GBS + cc]));
                #pragma unroll
                for (int mf = 0; mf < 2; mf++) {
                    mma16(acc[mf][2 * nfp],     af[mf], bf);
                    mma16(acc[mf][2 * nfp + 1], af[mf], bf + 2);
                }
            }
        }

        if (kt + 1 < KT) {
            if (kt + 2 < KT) cp_wait<1>(); else cp_wait<0>();
            __syncthreads();
        }
    }

    #pragma unroll
    for (int mf = 0; mf < 2; mf++)
        #pragma unroll
        for (int nf = 0; nf < 4; nf++) {
            int r = m0 + wm * 32 + mf * 16 + g;
            int c = n0 + wn * 32 + nf * 8 + tig * 2;
            if (HALF_OUT) {
                half* C = (half*)Cv;
                *(unsigned*)&C[(size_t)r * N + c] =
                    f2h2(acc[mf][nf][0], acc[mf][nf][1]);
                *(unsigned*)&C[(size_t)(r + 8) * N + c] =
                    f2h2(acc[mf][nf][2], acc[mf][nf][3]);
            } else {
                float* C = (float*)Cv;
                *(float2*)(C + (size_t)r * N + c) =
                    make_float2(acc[mf][nf][0], acc[mf][nf][1]);
                *(float2*)(C + (size_t)(r + 8) * N + c) =
                    make_float2(acc[mf][nf][2], acc[mf][nf][3]);
            }
        }
}

// Fused Q + KV projection: blockIdx.x 0..15 -> Wq, 16..23 -> Wkv. half out.
__global__ __launch_bounds__(256) void gemm_qkv(
    const half* __restrict__ x,
    const half* __restrict__ Wq, const half* __restrict__ Wkv,
    half* __restrict__ q, half* __restrict__ kvo)
{
    extern __shared__ half dsm[];
    half* sA = dsm;
    half* sB = dsm + 3 * SA_ST;
    int bx = blockIdx.x;
    if (bx < 16)
        gemm_core<true>(x, Wq, q, blockIdx.y * 128, bx * 64, HID, HID, sA, sB);
    else
        gemm_core<true>(x, Wkv, kvo, blockIdx.y * 128, (bx - 16) * 64, KVW, HID, sA, sB);
}

__global__ __launch_bounds__(256) void gemm_wo(
    const half* __restrict__ A, const half* __restrict__ B,
    float* __restrict__ C)
{
    extern __shared__ half dsm[];
    half* sA = dsm;
    half* sB = dsm + 3 * SA_ST;
    gemm_core<false>(A, B, C, blockIdx.y * 128, blockIdx.x * 64, HID, HID, sA, sB);
}

// ---------------------------------------------------------------------------
// fp16 flash attention: 64-row q-tiles, 128 threads (4 warps), cp.async dbuf
// K/V. Grid (T/64, H, B). Warp w owns q-rows [w*16, w*16+16).
// FA2-style register-P; paired ldsm4/ldsm4t for K and V fragments.
// (unchanged from R14 measured-best)
// ---------------------------------------------------------------------------
#define ASTR 72   // 64 + 8 pad (144B rows)

__global__ __launch_bounds__(128) void attn_h(
    const half* __restrict__ q, const half* __restrict__ kv,
    half* __restrict__ o)
{
    __shared__ half sQ[64 * ASTR];      // Q (prologue only)
    __shared__ half sK[2][64 * ASTR];   // [c][d]
    __shared__ half sV[2][64 * ASTR];   // [c][d]

    const int t = threadIdx.x, lane = t & 31, warp = t >> 5;
    const int g = lane >> 2, tig = lane & 3;
    const int qt = gridDim.x - 1 - blockIdx.x;  // long tiles first
    const int h = blockIdx.y, b = blockIdx.z;
    const int kvh = h >> 2;

    const size_t qbase = (size_t)b * TSEQ * HID + (size_t)h * HD;
    const half* kvp = kv + (size_t)b * TSEQ * KVW + (size_t)kvh * HD;

    const int kv_c = t >> 3, kv_ch = t & 7;

    auto issueKV = [&](int kt, int s) {
        #pragma unroll
        for (int u = 0; u < 4; u++) {
            int c = kv_c + u * 16;
            const half* rowp = kvp + (size_t)(kt * 64 + c) * KVW;
            cpa16(sptr(&sK[s][c * ASTR + kv_ch * 8]), rowp + kv_ch * 8);
            cpa16(sptr(&sV[s][c * ASTR + kv_ch * 8]), rowp + 256 + kv_ch * 8);
        }
        cp_commit();
    };

    issueKV(0, 0);

    // Q tile (pre-scaled by 1/8) -> sQ
    const half2 sc = __float2half2_rn(0.125f);
    #pragma unroll
    for (int u = 0; u < 4; u++) {
        int id = t + 128 * u;
        int r = id >> 3, dq = id & 7;
        uint4 v = *(const uint4*)(q + qbase + (size_t)(qt * 64 + r) * HID + dq * 8);
        half2* hv = (half2*)&v;
        #pragma unroll
        for (int i = 0; i < 4; i++) hv[i] = __hmul2(hv[i], sc);
        *(uint4*)&sQ[r * ASTR + dq * 8] = v;
    }
    cp_wait<0>();
    __syncthreads();

    // Q fragments to registers
    unsigned qa[4][4];
    {
        int row = warp * 16 + (lane & 15);
        int cb = (lane >> 4) * 8;
        #pragma unroll
        for (int ks = 0; ks < 4; ks++)
            ldsm4(qa[ks], sptr(&sQ[row * ASTR + ks * 16 + cb]));
    }

    float mr0 = -INFINITY, mr1 = -INFINITY, l0 = 0.f, l1 = 0.f;
    float O[8][4] = {};

    for (int kt = 0; kt <= qt; kt++) {
        int cur = kt & 1;
        if (kt < qt) issueKV(kt + 1, cur ^ 1);

        // S = Q K^T (warp: 16 x 64) — paired K frags via ldsm4
        float s[8][4] = {};
        #pragma unroll
        for (int ks = 0; ks < 4; ks++) {
            #pragma unroll
            for (int nfp = 0; nfp < 4; nfp++) {
                unsigned bf[4];
                int mat = lane >> 3;
                int rr = nfp * 16 + (mat >> 1) * 8 + (lane & 7);
                int cc = ks * 16 + (mat & 1) * 8;
                ldsm4(bf, sptr(&sK[cur][rr * ASTR + cc]));
                mma16(s[2 * nfp],     qa[ks], bf);
                mma16(s[2 * nfp + 1], qa[ks], bf + 2);
            }
        }

        // causal mask (diagonal tile only)
        if (kt == qt) {
            int r0 = qt * 64 + warp * 16 + g;
            #pragma unroll
            for (int nf = 0; nf < 8; nf++) {
                int col = kt * 64 + nf * 8 + tig * 2;
                if (col     > r0)     s[nf][0] = -INFINITY;
                if (col + 1 > r0)     s[nf][1] = -INFINITY;
                if (col     > r0 + 8) s[nf][2] = -INFINITY;
                if (col + 1 > r0 + 8) s[nf][3] = -INFINITY;
            }
        }

        // online softmax
        float mx0 = -INFINITY, mx1 = -INFINITY;
        #pragma unroll
        for (int nf = 0; nf < 8; nf++) {
            mx0 = fmaxf(mx0, fmaxf(s[nf][0], s[nf][1]));
            mx1 = fmaxf(mx1, fmaxf(s[nf][2], s[nf][3]));
        }
        #pragma unroll
        for (int off = 1; off < 4; off <<= 1) {
            mx0 = fmaxf(mx0, __shfl_xor_sync(0xffffffffu, mx0, off));
            mx1 = fmaxf(mx1, __shfl_xor_sync(0xffffffffu, mx1, off));
        }
        float nm0 = fmaxf(mr0, mx0), nm1 = fmaxf(mr1, mx1);
        float a0 = __expf(mr0 - nm0), a1 = __expf(mr1 - nm1);
        float rs0 = 0.f, rs1 = 0.f;
        #pragma unroll
        for (int nf = 0; nf < 8; nf++) {
            s[nf][0] = __expf(s[nf][0] - nm0);
            s[nf][1] = __expf(s[nf][1] - nm0);
            s[nf][2] = __expf(s[nf][2] - nm1);
            s[nf][3] = __expf(s[nf][3] - nm1);
            rs0 += s[nf][0] + s[nf][1];
            rs1 += s[nf][2] + s[nf][3];
        }
        #pragma unroll
        for (int off = 1; off < 4; off <<= 1) {
            rs0 += __shfl_xor_sync(0xffffffffu, rs0, off);
            rs1 += __shfl_xor_sync(0xffffffffu, rs1, off);
        }
        l0 = l0 * a0 + rs0;  l1 = l1 * a1 + rs1;
        mr0 = nm0;           mr1 = nm1;
        #pragma unroll
        for (int df = 0; df < 8; df++) {
            O[df][0] *= a0; O[df][1] *= a0;
            O[df][2] *= a1; O[df][3] *= a1;
        }

        // O += P @ V — P from S registers (C-frag == A-frag layout);
        // paired V frags via ldsm4t.
        #pragma unroll
        for (int ks = 0; ks < 4; ks++) {
            unsigned pa[4];
            pa[0] = f2h2(s[2 * ks][0],     s[2 * ks][1]);
            pa[1] = f2h2(s[2 * ks][2],     s[2 * ks][3]);
            pa[2] = f2h2(s[2 * ks + 1][0], s[2 * ks + 1][1]);
            pa[3] = f2h2(s[2 * ks + 1][2], s[2 * ks + 1][3]);
            #pragma unroll
            for (int dfp = 0; dfp < 4; dfp++) {
                unsigned bf[4];
                int mat = lane >> 3;
                int kr = ks * 16 + (mat & 1) * 8 + (lane & 7);
                int cc = dfp * 16 + (mat >> 1) * 8;
                ldsm4t(bf, sptr(&sV[cur][kr * ASTR + cc]));
                mma16(O[2 * dfp],     pa, bf);
                mma16(O[2 * dfp + 1], pa, bf + 2);
            }
        }

        if (kt < qt) {
            cp_wait<0>();
            __syncthreads();
        }
    }

    // epilogue: half output for Wo GEMM
    float inv0 = 1.f / l0, inv1 = 1.f / l1;
    int r = qt * 64 + warp * 16 + g;
    #pragma unroll
    for (int df = 0; df < 8; df++) {
        int c = h * HD + df * 8 + tig * 2;
        *(unsigned*)&o[(size_t)(b * TSEQ + r) * HID + c] =
            f2h2(O[df][0] * inv0, O[df][1] * inv0);
        *(unsigned*)&o[(size_t)(b * TSEQ + r + 8) * HID + c] =
            f2h2(O[df][2] * inv1, O[df][3] * inv1);
    }
}

// ---------------------------------------------------------------------------
extern "C" void kernel_launch(void* const* d_in, const int* in_sizes, int n_in,
                              void* d_out, int out_size)
{
    const float* x   = (const float*)d_in[0];
    const float* Wq  = (const float*)d_in[1];
    const float* Wkv = (const float*)d_in[2];
    const float* Wo  = (const float*)d_in[3];
    float* out = (float*)d_out;

    half *xh, *wqh, *wkvh, *woh, *qh, *kvh, *atth;
    cudaGetSymbolAddress((void**)&xh,   g_xh);
    cudaGetSymbolAddress((void**)&wqh,  g_wqh);
    cudaGetSymbolAddress((void**)&wkvh, g_wkvh);
    cudaGetSymbolAddress((void**)&woh,  g_woh);
    cudaGetSymbolAddress((void**)&qh,   g_qh);
    cudaGetSymbolAddress((void**)&kvh,  g_kvh);
    cudaGetSymbolAddress((void**)&atth, g_atth);

    cudaFuncSetAttribute(gemm_qkv,
                         cudaFuncAttributeMaxDynamicSharedMemorySize, GSMEM);
    cudaFuncSetAttribute(gemm_wo,
                         cudaFuncAttributeMaxDynamicSharedMemorySize, GSMEM);

    conv_all<<<(CNT + 255) / 256, 256>>>(
        (const float4*)x, (const float4*)Wq, (const float4*)Wkv, (const float4*)Wo,
        (uint2*)xh, (uint2*)wqh, (uint2*)wkvh, (uint2*)woh);

    gemm_qkv<<<dim3(24, BT / 128), 256, GSMEM>>>(xh, wqh, wkvh, qh, kvh);
    attn_h<<<dim3(TSEQ / 64, 16, 2), 128>>>(qh, kvh, atth);
    gemm_wo<<<dim3(HID / 64, BT / 128), 256, GSMEM>>>(atth, woh, out);
}

// round 17
// speedup vs baseline: 1.0870x; 1.0870x over previous
#include <cuda_runtime.h>
#include <cuda_fp16.h>
#include <math.h>

#define BT   4096
#define HID  1024
#define TSEQ 2048
#define KVW  512
#define HD   64

// fp16 scratch (device globals — no allocation allowed)
__device__ __align__(256) half g_xh[(size_t)BT * HID];
__device__ __align__(256) half g_wqh[(size_t)HID * HID];
__device__ __align__(256) half g_wkvh[(size_t)HID * KVW];
__device__ __align__(256) half g_woh[(size_t)HID * HID];
__device__ __align__(256) half g_qh[(size_t)BT * HID];
__device__ __align__(256) half g_kvh[(size_t)BT * KVW];
__device__ __align__(256) half g_atth[(size_t)BT * HID];

// ---------------------------------------------------------------------------
// helpers
// ---------------------------------------------------------------------------
__device__ __forceinline__ unsigned f2h2(float a, float b) {
    half2 h = __float22half2_rn(make_float2(a, b));
    return *(unsigned*)&h;
}
__device__ __forceinline__ unsigned hex2(unsigned x) {
    unsigned r;
    asm("ex2.approx.f16x2 %0, %1;" : "=r"(r) : "r"(x));
    return r;
}
__device__ __forceinline__ void mma16(float* d, const unsigned* a, const unsigned* b) {
    asm volatile(
        "mma.sync.aligned.m16n8k16.row.col.f32.f16.f16.f32 "
        "{%0,%1,%2,%3},{%4,%5,%6,%7},{%8,%9},{%0,%1,%2,%3};\n"
        : "+f"(d[0]), "+f"(d[1]), "+f"(d[2]), "+f"(d[3])
        : "r"(a[0]), "r"(a[1]), "r"(a[2]), "r"(a[3]), "r"(b[0]), "r"(b[1]));
}
__device__ __forceinline__ void ldsm4(unsigned* r, unsigned addr) {
    asm volatile("ldmatrix.sync.aligned.m8n8.x4.shared.b16 {%0,%1,%2,%3}, [%4];"
                 : "=r"(r[0]), "=r"(r[1]), "=r"(r[2]), "=r"(r[3]) : "r"(addr));
}
__device__ __forceinline__ void ldsm4t(unsigned* r, unsigned addr) {
    asm volatile("ldmatrix.sync.aligned.m8n8.x4.trans.shared.b16 {%0,%1,%2,%3}, [%4];"
                 : "=r"(r[0]), "=r"(r[1]), "=r"(r[2]), "=r"(r[3]) : "r"(addr));
}
__device__ __forceinline__ unsigned sptr(const void* p) {
    return (unsigned)__cvta_generic_to_shared(p);
}
__device__ __forceinline__ void cpa16(unsigned dst, const void* src) {
    asm volatile("cp.async.cg.shared.global [%0], [%1], 16;" :: "r"(dst), "l"(src));
}
__device__ __forceinline__ void cp_commit() {
    asm volatile("cp.async.commit_group;");
}
template<int N> __device__ __forceinline__ void cp_wait() {
    asm volatile("cp.async.wait_group %0;" :: "n"(N));
}

// ---------------------------------------------------------------------------
// fused fp32 -> fp16 convert for all 4 tensors (one launch)
// ---------------------------------------------------------------------------
#define CN0 (BT * HID / 4)     // x
#define CN1 (HID * HID / 4)    // Wq
#define CN2 (HID * KVW / 4)    // Wkv
#define CN3 (HID * HID / 4)    // Wo
#define CNT (CN0 + CN1 + CN2 + CN3)

__global__ __launch_bounds__(256) void conv_all(
    const float4* __restrict__ x,  const float4* __restrict__ wq,
    const float4* __restrict__ wkv, const float4* __restrict__ wo,
    uint2* __restrict__ xh, uint2* __restrict__ wqh,
    uint2* __restrict__ wkvh, uint2* __restrict__ woh)
{
    int i = blockIdx.x * 256 + threadIdx.x;
    const float4* src;
    uint2* dst;
    int j;
    if (i < CN0)                  { src = x;   dst = xh;   j = i; }
    else if (i < CN0 + CN1)       { src = wq;  dst = wqh;  j = i - CN0; }
    else if (i < CN0 + CN1 + CN2) { src = wkv; dst = wkvh; j = i - CN0 - CN1; }
    else if (i < CNT)             { src = wo;  dst = woh;  j = i - CN0 - CN1 - CN2; }
    else return;
    float4 v = src[j];
    dst[j] = make_uint2(f2h2(v.x, v.y), f2h2(v.z, v.w));
}

// ---------------------------------------------------------------------------
// fp16 GEMM, cp.async 2-stage, BK=64 (R14 measured-best config).
// C[M,N] = A[M,K] @ B[K,N]. BM=128, BN=64, BK=64, 256 thr, 8 warps (4m x 2n).
// ---------------------------------------------------------------------------
#define GAS 72   // sA row stride (halves): 64 + 8 pad (144B rows)
#define GBS 72   // sB row stride (halves): 64 + 8 pad
#define SA_ST (128 * GAS)
#define SB_ST (64 * GBS)
#define GSMEM ((2 * (SA_ST + SB_ST)) * 2)   // bytes (2 stages)

template<bool HALF_OUT>
__device__ __forceinline__ void gemm_core(
    const half* __restrict__ A, const half* __restrict__ B,
    void* __restrict__ Cv, int m0, int n0, int N, int K,
    half* sA, half* sB)
{
    const int t = threadIdx.x, lane = t & 31, warp = t >> 5;
    const int wm = warp & 3, wn = warp >> 2;
    const int g = lane >> 2, tig = lane & 3;
    const int KT = K >> 6;

    const int ld_row = t >> 3, ld_ch = t & 7;   // 8 chunks (of 8 halves) per row

    auto issue = [&](int kt, int s) {
        int k0 = kt * 64;
        half* dA = sA + s * SA_ST;
        half* dB = sB + s * SB_ST;
        #pragma unroll
        for (int u = 0; u < 4; u++) {            // A: 128 rows x 64 halves
            int row = ld_row + u * 32;
            cpa16(sptr(&dA[row * GAS + ld_ch * 8]),
                  A + (size_t)(m0 + row) * K + k0 + ld_ch * 8);
        }
        #pragma unroll
        for (int u = 0; u < 2; u++) {            // B: 64 rows x 64 halves
            int row = ld_row + u * 32;
            cpa16(sptr(&dB[row * GBS + ld_ch * 8]),
                  B + (size_t)(k0 + row) * N + n0 + ld_ch * 8);
        }
        cp_commit();
    };

    float acc[2][4][4] = {};

    issue(0, 0);
    cp_wait<0>();
    __syncthreads();

    for (int kt = 0; kt < KT; kt++) {
        int cur = kt & 1;
        if (kt + 1 < KT) issue(kt + 1, cur ^ 1);

        half* cA = sA + cur * SA_ST;
        half* cB = sB + cur * SB_ST;

        #pragma unroll
        for (int ks = 0; ks < 4; ks++) {
            unsigned af[2][4];
            #pragma unroll
            for (int mf = 0; mf < 2; mf++) {
                int row = wm * 32 + mf * 16 + (lane & 15);
                int col = ks * 16 + (lane >> 4) * 8;
                ldsm4(af[mf], sptr(&cA[row * GAS + col]));
            }
            #pragma unroll
            for (int nfp = 0; nfp < 2; nfp++) {
                // paired B frags (nf=2*nfp, 2*nfp+1) via one ldsm4t
                unsigned bf[4];
                int mat = lane >> 3;
                int kr = ks * 16 + (mat & 1) * 8 + (lane & 7);
                int cc = wn * 32 + nfp * 16 + (mat >> 1) * 8;
                ldsm4t(bf, sptr(&cB[kr * GBS + cc]));
                #pragma unroll
                for (int mf = 0; mf < 2; mf++) {
                    mma16(acc[mf][2 * nfp],     af[mf], bf);
                    mma16(acc[mf][2 * nfp + 1], af[mf], bf + 2);
                }
            }
        }

        if (kt + 1 < KT) {
            cp_wait<0>();
            __syncthreads();
        }
    }

    #pragma unroll
    for (int mf = 0; mf < 2; mf++)
        #pragma unroll
        for (int nf = 0; nf < 4; nf++) {
            int r = m0 + wm * 32 + mf * 16 + g;
            int c = n0 + wn * 32 + nf * 8 + tig * 2;
            if (HALF_OUT) {
                half* C = (half*)Cv;
                *(unsigned*)&C[(size_t)r * N + c] =
                    f2h2(acc[mf][nf][0], acc[mf][nf][1]);
                *(unsigned*)&C[(size_t)(r + 8) * N + c] =
                    f2h2(acc[mf][nf][2], acc[mf][nf][3]);
            } else {
                float* C = (float*)Cv;
                *(float2*)(C + (size_t)r * N + c) =
                    make_float2(acc[mf][nf][0], acc[mf][nf][1]);
                *(float2*)(C + (size_t)(r + 8) * N + c) =
                    make_float2(acc[mf][nf][2], acc[mf][nf][3]);
            }
        }
}

// Fused Q + KV projection: blockIdx.x 0..15 -> Wq, 16..23 -> Wkv. half out.
__global__ __launch_bounds__(256) void gemm_qkv(
    const half* __restrict__ x,
    const half* __restrict__ Wq, const half* __restrict__ Wkv,
    half* __restrict__ q, half* __restrict__ kvo)
{
    extern __shared__ half dsm[];
    half* sA = dsm;
    half* sB = dsm + 2 * SA_ST;
    int bx = blockIdx.x;
    if (bx < 16)
        gemm_core<true>(x, Wq, q, blockIdx.y * 128, bx * 64, HID, HID, sA, sB);
    else
        gemm_core<true>(x, Wkv, kvo, blockIdx.y * 128, (bx - 16) * 64, KVW, HID, sA, sB);
}

__global__ __launch_bounds__(256) void gemm_wo(
    const half* __restrict__ A, const half* __restrict__ B,
    float* __restrict__ C)
{
    extern __shared__ half dsm[];
    half* sA = dsm;
    half* sB = dsm + 2 * SA_ST;
    gemm_core<false>(A, B, C, blockIdx.y * 128, blockIdx.x * 64, HID, HID, sA, sB);
}

// ---------------------------------------------------------------------------
// fp16 flash attention: 64-row q-tiles, 128 threads (4 warps), cp.async dbuf
// K/V. Grid (T/64, H, B). Warp w owns q-rows [w*16, w*16+16).
// FA2 register-P; softmax exp via ex2.approx.f16x2 (2 exps/MUFU, output IS
// the PV A-fragment); row-sum l via ones-column MMA (exact fp32 sum of the
// same fp16 P used in PV).
// ---------------------------------------------------------------------------
#define ASTR 72   // 64 + 8 pad (144B rows)

__global__ __launch_bounds__(128) void attn_h(
    const half* __restrict__ q, const half* __restrict__ kv,
    half* __restrict__ o)
{
    __shared__ half sQ[64 * ASTR];      // Q (prologue only)
    __shared__ half sK[2][64 * ASTR];   // [c][d]
    __shared__ half sV[2][64 * ASTR];   // [c][d]

    const int t = threadIdx.x, lane = t & 31, warp = t >> 5;
    const int g = lane >> 2, tig = lane & 3;
    const int qt = gridDim.x - 1 - blockIdx.x;  // long tiles first
    const int h = blockIdx.y, b = blockIdx.z;
    const int kvh = h >> 2;

    const size_t qbase = (size_t)b * TSEQ * HID + (size_t)h * HD;
    const half* kvp = kv + (size_t)b * TSEQ * KVW + (size_t)kvh * HD;

    const int kv_c = t >> 3, kv_ch = t & 7;

    auto issueKV = [&](int kt, int s) {
        #pragma unroll
        for (int u = 0; u < 4; u++) {
            int c = kv_c + u * 16;
            const half* rowp = kvp + (size_t)(kt * 64 + c) * KVW;
            cpa16(sptr(&sK[s][c * ASTR + kv_ch * 8]), rowp + kv_ch * 8);
            cpa16(sptr(&sV[s][c * ASTR + kv_ch * 8]), rowp + 256 + kv_ch * 8);
        }
        cp_commit();
    };

    issueKV(0, 0);

    // Q tile (pre-scaled by 1/8) -> sQ
    const half2 sc = __float2half2_rn(0.125f);
    #pragma unroll
    for (int u = 0; u < 4; u++) {
        int id = t + 128 * u;
        int r = id >> 3, dq = id & 7;
        uint4 v = *(const uint4*)(q + qbase + (size_t)(qt * 64 + r) * HID + dq * 8);
        half2* hv = (half2*)&v;
        #pragma unroll
        for (int i = 0; i < 4; i++) hv[i] = __hmul2(hv[i], sc);
        *(uint4*)&sQ[r * ASTR + dq * 8] = v;
    }
    cp_wait<0>();
    __syncthreads();

    // Q fragments to registers
    unsigned qa[4][4];
    {
        int row = warp * 16 + (lane & 15);
        int cb = (lane >> 4) * 8;
        #pragma unroll
        for (int ks = 0; ks < 4; ks++)
            ldsm4(qa[ks], sptr(&sQ[row * ASTR + ks * 16 + cb]));
    }

    const float L2E = 1.4426950408889634f;
    const unsigned one2 = 0x3C003C00u;          // half2(1.0, 1.0)
    const unsigned onesb[2] = {one2, one2};

    float mr0 = -INFINITY, mr1 = -INFINITY, l0 = 0.f, l1 = 0.f;
    float O[8][4] = {};

    for (int kt = 0; kt <= qt; kt++) {
        int cur = kt & 1;
        if (kt < qt) issueKV(kt + 1, cur ^ 1);

        // S = Q K^T (warp: 16 x 64) — paired K frags via ldsm4
        float s[8][4] = {};
        #pragma unroll
        for (int ks = 0; ks < 4; ks++) {
            #pragma unroll
            for (int nfp = 0; nfp < 4; nfp++) {
                unsigned bf[4];
                int mat = lane >> 3;
                int rr = nfp * 16 + (mat >> 1) * 8 + (lane & 7);
                int cc = ks * 16 + (mat & 1) * 8;
                ldsm4(bf, sptr(&sK[cur][rr * ASTR + cc]));
                mma16(s[2 * nfp],     qa[ks], bf);
                mma16(s[2 * nfp + 1], qa[ks], bf + 2);
            }
        }

        // causal mask (diagonal tile only)
        if (kt == qt) {
            int r0 = qt * 64 + warp * 16 + g;
            #pragma unroll
            for (int nf = 0; nf < 8; nf++) {
                int col = kt * 64 + nf * 8 + tig * 2;
                if (col     > r0)     s[nf][0] = -INFINITY;
                if (col + 1 > r0)     s[nf][1] = -INFINITY;
                if (col     > r0 + 8) s[nf][2] = -INFINITY;
                if (col + 1 > r0 + 8) s[nf][3] = -INFINITY;
            }
        }

        // online softmax — row max in fp32
        float mx0 = -INFINITY, mx1 = -INFINITY;
        #pragma unroll
        for (int nf = 0; nf < 8; nf++) {
            mx0 = fmaxf(mx0, fmaxf(s[nf][0], s[nf][1]));
            mx1 = fmaxf(mx1, fmaxf(s[nf][2], s[nf][3]));
        }
        #pragma unroll
        for (int off = 1; off < 4; off <<= 1) {
            mx0 = fmaxf(mx0, __shfl_xor_sync(0xffffffffu, mx0, off));
            mx1 = fmaxf(mx1, __shfl_xor_sync(0xffffffffu, mx1, off));
        }
        float nm0 = fmaxf(mr0, mx0), nm1 = fmaxf(mr1, mx1);
        float a0 = __expf(mr0 - nm0), a1 = __expf(mr1 - nm1);
        float b0 = nm0 * L2E, b1 = nm1 * L2E;

        // P = 2^((s - nm)*log2e) via ex2.approx.f16x2 — output IS the PV
        // A-fragment (C-frag == A-frag layout).
        unsigned pa[4][4];
        #pragma unroll
        for (int nf = 0; nf < 8; nf++) {
            unsigned lo = f2h2(fmaf(s[nf][0], L2E, -b0),
                               fmaf(s[nf][1], L2E, -b0));
            unsigned hi = f2h2(fmaf(s[nf][2], L2E, -b1),
                               fmaf(s[nf][3], L2E, -b1));
            pa[nf >> 1][(nf & 1) * 2]     = hex2(lo);
            pa[nf >> 1][(nf & 1) * 2 + 1] = hex2(hi);
        }

        // row-sum via ones-column MMA: rsv[0]=rowsum(g), rsv[2]=rowsum(g+8)
        float rsv[4] = {0.f, 0.f, 0.f, 0.f};
        #pragma unroll
        for (int ks = 0; ks < 4; ks++)
            mma16(rsv, pa[ks], onesb);

        l0 = l0 * a0 + rsv[0];
        l1 = l1 * a1 + rsv[2];
        mr0 = nm0;
        mr1 = nm1;
        #pragma unroll
        for (int df = 0; df < 8; df++) {
            O[df][0] *= a0; O[df][1] *= a0;
            O[df][2] *= a1; O[df][3] *= a1;
        }

        // O += P @ V — paired V frags via ldsm4t.
        #pragma unroll
        for (int ks = 0; ks < 4; ks++) {
            #pragma unroll
            for (int dfp = 0; dfp < 4; dfp++) {
                unsigned bf[4];
                int mat = lane >> 3;
                int kr = ks * 16 + (mat & 1) * 8 + (lane & 7);
                int cc = dfp * 16 + (mat >> 1) * 8;
                ldsm4t(bf, sptr(&sV[cur][kr * ASTR + cc]));
                mma16(O[2 * dfp],     pa[ks], bf);
                mma16(O[2 * dfp + 1], pa[ks], bf + 2);
            }
        }

        if (kt < qt) {
            cp_wait<0>();
            __syncthreads();
        }
    }

    // epilogue: half output for Wo GEMM
    float inv0 = 1.f / l0, inv1 = 1.f / l1;
    int r = qt * 64 + warp * 16 + g;
    #pragma unroll
    for (int df = 0; df < 8; df++) {
        int c = h * HD + df * 8 + tig * 2;
        *(unsigned*)&o[(size_t)(b * TSEQ + r) * HID + c] =
            f2h2(O[df][0] * inv0, O[df][1] * inv0);
        *(unsigned*)&o[(size_t)(b * TSEQ + r + 8) * HID + c] =
            f2h2(O[df][2] * inv1, O[df][3] * inv1);
    }
}

// ---------------------------------------------------------------------------
extern "C" void kernel_launch(void* const* d_in, const int* in_sizes, int n_in,
                              void* d_out, int out_size)
{
    const float* x   = (const float*)d_in[0];
    const float* Wq  = (const float*)d_in[1];
    const float* Wkv = (const float*)d_in[2];
    const float* Wo  = (const float*)d_in[3];
    float* out = (float*)d_out;

    half *xh, *wqh, *wkvh, *woh, *qh, *kvh, *atth;
    cudaGetSymbolAddress((void**)&xh,   g_xh);
    cudaGetSymbolAddress((void**)&wqh,  g_wqh);
    cudaGetSymbolAddress((void**)&wkvh, g_wkvh);
    cudaGetSymbolAddress((void**)&woh,  g_woh);
    cudaGetSymbolAddress((void**)&qh,   g_qh);
    cudaGetSymbolAddress((void**)&kvh,  g_kvh);
    cudaGetSymbolAddress((void**)&atth, g_atth);

    cudaFuncSetAttribute(gemm_qkv,
                         cudaFuncAttributeMaxDynamicSharedMemorySize, GSMEM);
    cudaFuncSetAttribute(gemm_wo,
                         cudaFuncAttributeMaxDynamicSharedMemorySize, GSMEM);

    conv_all<<<(CNT + 255) / 256, 256>>>(
        (const float4*)x, (const float4*)Wq, (const float4*)Wkv, (const float4*)Wo,
        (uint2*)xh, (uint2*)wqh, (uint2*)wkvh, (uint2*)woh);

    gemm_qkv<<<dim3(24, BT / 128), 256, GSMEM>>>(xh, wqh, wkvh, qh, kvh);
    attn_h<<<dim3(TSEQ / 64, 16, 2), 128>>>(qh, kvh, atth);
    gemm_wo<<<dim3(HID / 64, BT / 128), 256, GSMEM>>>(atth, woh, out);
}